// round 8
// baseline (speedup 1.0000x reference)
#include <cuda_runtime.h>

#define IMG_B 8
#define IMG_H 100
#define IMG_W 100
#define IMG_C 256
#define OUT_HW 7
#define CELLS 49
#define N_CELLS (2000 * CELLS)      // 98000

#define TS 8                        // tile size (pixels)
#define TG 13                       // tiles per dim
#define NT (IMG_B * TG * TG)        // 1352
#define HALO 9
#define CAP 1024                    // list capacity per tile
#define CHUNK 64
#define NCHUNK 4                    // last chunk loops to cnt
#define HC 128                      // channels per block (half)
#define SMEM_BYTES (HALO * HALO * HC * 4)   // 41472 -> 5 blocks/SM

__device__ int g_cnt[NT];
__device__ int g_list[NT * CAP];

// ---- coordinate math (must match reference exactly) ----
struct CellGeo {
    int b, ty, by, tx, bx;
    float ly, lx;
    bool valid;
};

__device__ __forceinline__ CellGeo cell_geo(const float* __restrict__ rois, int cell)
{
    int roi = cell / CELLS;
    int rem = cell - roi * CELLS;
    int oy = rem / OUT_HW;
    int ox = rem - oy * OUT_HW;

    const float* r = rois + roi * 5;
    float rb  = __ldg(r + 0);
    float rx1 = __ldg(r + 1);
    float ry1 = __ldg(r + 2);
    float rx2 = __ldg(r + 3);
    float ry2 = __ldg(r + 4);

    float x1 = rx1 * (1.0f / IMG_W);
    float x2 = rx2 * (1.0f / IMG_W);
    float y1 = ry1 * (1.0f / IMG_H);
    float y2 = ry2 * (1.0f / IMG_H);

    float in_y = y1 * (float)(IMG_H - 1)
               + (float)oy * ((y2 - y1) * (float)(IMG_H - 1) / (float)(OUT_HW - 1));
    float in_x = x1 * (float)(IMG_W - 1)
               + (float)ox * ((x2 - x1) * (float)(IMG_W - 1) / (float)(OUT_HW - 1));

    CellGeo g;
    g.b = (int)rb;
    g.valid = (in_y >= 0.0f) && (in_y <= (float)(IMG_H - 1)) &&
              (in_x >= 0.0f) && (in_x <= (float)(IMG_W - 1));

    float fy = floorf(in_y);
    float fx = floorf(in_x);
    g.ly = in_y - fy;
    g.lx = in_x - fx;
    g.ty = min(max((int)fy, 0), IMG_H - 1);
    g.by = min(max((int)ceilf(in_y), 0), IMG_H - 1);
    g.tx = min(max((int)fx, 0), IMG_W - 1);
    g.bx = min(max((int)ceilf(in_x), 0), IMG_W - 1);
    return g;
}

__device__ __forceinline__ int tile_of(const CellGeo& g)
{
    return (g.b * TG + (g.ty >> 3)) * TG + (g.tx >> 3);
}

// ---- pass 1: bin cells (counters pre-zeroed by memset node) ----
__global__ void k_bin(const float* __restrict__ rois)
{
    int cell = blockIdx.x * blockDim.x + threadIdx.x;
    if (cell >= N_CELLS) return;
    CellGeo g = cell_geo(rois, cell);
    int t = tile_of(g);
    int pos = atomicAdd(&g_cnt[t], 1);
    if (pos < CAP) g_list[t * CAP + pos] = cell;
}

// ---- pass 2: per-(tile, channel-half, chunk) processing ----
// 256 threads, 40.5KB smem (9x9 px x 128ch), 5 blocks/SM.
__global__ void __launch_bounds__(256, 5)
k_process(const float* __restrict__ img,
          const float* __restrict__ rois,
          float* __restrict__ out)
{
    int bid   = blockIdx.x;
    int t     = bid / (2 * NCHUNK);
    int sub   = bid - t * (2 * NCHUNK);
    int half  = sub & 1;
    int chunk = sub >> 1;

    int cnt = min(g_cnt[t], CAP);
    int i_beg = chunk * CHUNK;
    if (i_beg >= cnt) return;
    int i_end = (chunk == NCHUNK - 1) ? cnt : min(cnt, i_beg + CHUNK);

    int b   = t / (TG * TG);
    int rr  = t - b * (TG * TG);
    int y0  = (rr / TG) * TS;
    int x0  = (rr % TG) * TS;
    int nrows = min(HALO, IMG_H - y0);
    int ncols = min(HALO, IMG_W - x0);

    extern __shared__ float sm[];   // [dy][dx][128 ch]

    // cooperative tile load: one pixel-half = 512B; warp covers it per access
    {
        int ch0 = half * HC;
        for (int dy = 0; dy < nrows; dy++) {
            const float4* src = (const float4*)(img
                + ((size_t)(b * IMG_H + y0 + dy) * IMG_W + x0) * IMG_C + ch0);
            float4* dst = (float4*)(sm + (size_t)dy * HALO * HC);
            int row_f4 = ncols * (HC / 4);     // <=288; pixel stride src: 64 f4
            for (int j = threadIdx.x; j < row_f4; j += 256) {
                int dx = j >> 5;               // 32 float4 per pixel-half
                int k  = j & 31;
                dst[(size_t)dx * (HC / 4) + k] = __ldg(src + (size_t)dx * (IMG_C / 4) + k);
            }
        }
    }
    __syncthreads();

    int warp = threadIdx.x >> 5;
    int lane = threadIdx.x & 31;
    int chw  = lane * 4;                       // float offset within half

    const int* list = g_list + t * CAP;

    for (int i = i_beg + warp; i < i_end; i += 8) {
        int cell = list[i];
        CellGeo g = cell_geo(rois, cell);

        float* ocell = out + (size_t)cell * IMG_C + half * HC + chw;

        if (!g.valid) {
            *(float4*)ocell = make_float4(0.f, 0.f, 0.f, 0.f);
            continue;
        }

        int sdy_t = g.ty - y0, sdy_b = g.by - y0;
        int sdx_t = g.tx - x0, sdx_b = g.bx - x0;

        const float* s_tl = sm + (size_t)(sdy_t * HALO + sdx_t) * HC + chw;
        const float* s_tr = sm + (size_t)(sdy_t * HALO + sdx_b) * HC + chw;
        const float* s_bl = sm + (size_t)(sdy_b * HALO + sdx_t) * HC + chw;
        const float* s_br = sm + (size_t)(sdy_b * HALO + sdx_b) * HC + chw;

        float lx = g.lx, ly = g.ly;

        float4 tl = *(const float4*)s_tl;
        float4 tr = *(const float4*)s_tr;
        float4 bl = *(const float4*)s_bl;
        float4 br = *(const float4*)s_br;
        float4 res;
        {
            float top, bot;
            top = tl.x + (tr.x - tl.x) * lx;
            bot = bl.x + (br.x - bl.x) * lx;
            res.x = top + (bot - top) * ly;
            top = tl.y + (tr.y - tl.y) * lx;
            bot = bl.y + (br.y - bl.y) * lx;
            res.y = top + (bot - top) * ly;
            top = tl.z + (tr.z - tl.z) * lx;
            bot = bl.z + (br.z - bl.z) * lx;
            res.z = top + (bot - top) * ly;
            top = tl.w + (tr.w - tl.w) * lx;
            bot = bl.w + (br.w - bl.w) * lx;
            res.w = top + (bot - top) * ly;
        }
        *(float4*)ocell = res;
    }
}

extern "C" void kernel_launch(void* const* d_in, const int* in_sizes, int n_in,
                              void* d_out, int out_size)
{
    const float* img  = (const float*)d_in[0];
    const float* rois = (const float*)d_in[1];
    float* out = (float*)d_out;

    cudaFuncSetAttribute(k_process, cudaFuncAttributeMaxDynamicSharedMemorySize,
                         SMEM_BYTES);

    void* cnt_ptr = nullptr;
    cudaGetSymbolAddress(&cnt_ptr, g_cnt);
    cudaMemsetAsync(cnt_ptr, 0, NT * sizeof(int), 0);

    k_bin<<<(N_CELLS + 255) / 256, 256>>>(rois);
    k_process<<<NT * 2 * NCHUNK, 256, SMEM_BYTES>>>(img, rois, out);
}

// round 9
// speedup vs baseline: 1.3406x; 1.3406x over previous
#include <cuda_runtime.h>

#define IMG_B 8
#define IMG_H 100
#define IMG_W 100
#define IMG_C 256
#define OUT_HW 7
#define CELLS 49
#define N_CELLS (2000 * CELLS)      // 98000

#define TS 8                        // tile size (pixels)
#define TG 13                       // tiles per dim
#define NT (IMG_B * TG * TG)        // 1352
#define HALO 9
#define CAP 1024
#define HC 128                      // channels per block (half)
#define SMEM_BYTES (HALO * HALO * HC * 4)   // 41472 -> 5 blocks/SM

__device__ int  g_cnt[NT];
__device__ int4 g_geo[NT * CAP];    // 22 MB: {cell|valid<<30, packed(ty,by,tx,bx), ly, lx}

// 256-bit image load (evict_last hint; legal v8 form on sm_103)
__device__ __forceinline__ void ldg256(const float* p, float4* d) {
    unsigned r0, r1, r2, r3, r4, r5, r6, r7;
    asm volatile("ld.global.nc.L2::evict_last.v8.b32 {%0,%1,%2,%3,%4,%5,%6,%7}, [%8];"
                 : "=r"(r0), "=r"(r1), "=r"(r2), "=r"(r3),
                   "=r"(r4), "=r"(r5), "=r"(r6), "=r"(r7) : "l"(p));
    d[0] = make_float4(__uint_as_float(r0), __uint_as_float(r1),
                       __uint_as_float(r2), __uint_as_float(r3));
    d[1] = make_float4(__uint_as_float(r4), __uint_as_float(r5),
                       __uint_as_float(r6), __uint_as_float(r7));
}
// write-through store: do not allocate the 100MB output stream in L2
__device__ __forceinline__ void stg_wt(float* p, float4 v) {
    asm volatile("st.global.wt.v4.f32 [%0], {%1,%2,%3,%4};"
                 :: "l"(p), "f"(v.x), "f"(v.y), "f"(v.z), "f"(v.w) : "memory");
}

// ---- pass 1: compute geometry once per cell, bin into per-tile lists ----
__global__ void k_bin(const float* __restrict__ rois)
{
    int cell = blockIdx.x * blockDim.x + threadIdx.x;
    if (cell >= N_CELLS) return;

    int roi = cell / CELLS;
    int rem = cell - roi * CELLS;
    int oy = rem / OUT_HW;
    int ox = rem - oy * OUT_HW;

    const float* r = rois + roi * 5;
    float rb  = __ldg(r + 0);
    float rx1 = __ldg(r + 1);
    float ry1 = __ldg(r + 2);
    float rx2 = __ldg(r + 3);
    float ry2 = __ldg(r + 4);

    float x1 = rx1 * (1.0f / IMG_W);
    float x2 = rx2 * (1.0f / IMG_W);
    float y1 = ry1 * (1.0f / IMG_H);
    float y2 = ry2 * (1.0f / IMG_H);

    float in_y = y1 * (float)(IMG_H - 1)
               + (float)oy * ((y2 - y1) * (float)(IMG_H - 1) / (float)(OUT_HW - 1));
    float in_x = x1 * (float)(IMG_W - 1)
               + (float)ox * ((x2 - x1) * (float)(IMG_W - 1) / (float)(OUT_HW - 1));

    bool valid = (in_y >= 0.0f) && (in_y <= (float)(IMG_H - 1)) &&
                 (in_x >= 0.0f) && (in_x <= (float)(IMG_W - 1));

    float fy = floorf(in_y);
    float fx = floorf(in_x);
    float ly = in_y - fy;
    float lx = in_x - fx;
    int ty = min(max((int)fy, 0), IMG_H - 1);
    int by = min(max((int)ceilf(in_y), 0), IMG_H - 1);
    int tx = min(max((int)fx, 0), IMG_W - 1);
    int bx = min(max((int)ceilf(in_x), 0), IMG_W - 1);

    int b = (int)rb;
    int t = (b * TG + (ty >> 3)) * TG + (tx >> 3);

    int4 rec;
    rec.x = cell | (valid ? (1 << 30) : 0);
    rec.y = ty | (by << 8) | (tx << 16) | (bx << 24);
    rec.z = __float_as_int(ly);
    rec.w = __float_as_int(lx);

    int pos = atomicAdd(&g_cnt[t], 1);
    if (pos < CAP) g_geo[t * CAP + pos] = rec;
}

// ---- pass 2: one block per (tile, channel-half) ----
// 256 threads, 40.5KB smem, 5 blocks/SM. Every image byte loaded once chip-wide.
__global__ void __launch_bounds__(256, 5)
k_process(const float* __restrict__ img, float* __restrict__ out)
{
    int bid  = blockIdx.x;
    int t    = bid >> 1;
    int half = bid & 1;

    int cnt = min(g_cnt[t], CAP);
    if (cnt == 0) return;

    int b   = t / (TG * TG);
    int rr  = t - b * (TG * TG);
    int y0  = (rr / TG) * TS;
    int x0  = (rr % TG) * TS;
    int nrows = min(HALO, IMG_H - y0);
    int ncols = min(HALO, IMG_W - x0);

    extern __shared__ float sm[];   // [dy][dx][128 ch], pixel pitch HC

    // cooperative half-tile load, 32B units; each unit: k in 0..15 of a pixel-half
    {
        const float* src0 = img
            + ((size_t)(b * IMG_H + y0) * IMG_W + x0) * IMG_C + half * HC;
        int units_row = ncols * 16;            // 32B units per image row
        int total     = nrows * units_row;
        for (int i = threadIdx.x; i < total; i += 256) {
            int dy = i / units_row;
            int rst = i - dy * units_row;
            int dx = rst >> 4;
            int k  = rst & 15;
            const float* s = src0 + (size_t)(dy * IMG_W + dx) * IMG_C + k * 8;
            ldg256(s, (float4*)(sm + ((size_t)(dy * HALO + dx) * HC + k * 8)));
        }
    }
    __syncthreads();

    int warp = threadIdx.x >> 5;
    int lane = threadIdx.x & 31;
    int chw  = lane * 4;                       // float offset within the half

    const int4* list = g_geo + t * CAP;

    for (int i = warp; i < cnt; i += 8) {
        int4 rec = __ldg(list + i);
        int cell  = rec.x & 0x3FFFFFFF;
        bool valid = (rec.x >> 30) & 1;

        float* ocell = out + (size_t)cell * IMG_C + half * HC + chw;

        if (!valid) {
            stg_wt(ocell, make_float4(0.f, 0.f, 0.f, 0.f));
            continue;
        }

        int ty = rec.y & 0xFF;
        int by = (rec.y >> 8) & 0xFF;
        int tx = (rec.y >> 16) & 0xFF;
        int bx = (rec.y >> 24) & 0xFF;
        float ly = __int_as_float(rec.z);
        float lx = __int_as_float(rec.w);

        int sdy_t = ty - y0, sdy_b = by - y0;
        int sdx_t = tx - x0, sdx_b = bx - x0;

        const float* s_tl = sm + (size_t)(sdy_t * HALO + sdx_t) * HC + chw;
        const float* s_tr = sm + (size_t)(sdy_t * HALO + sdx_b) * HC + chw;
        const float* s_bl = sm + (size_t)(sdy_b * HALO + sdx_t) * HC + chw;
        const float* s_br = sm + (size_t)(sdy_b * HALO + sdx_b) * HC + chw;

        float4 tl = *(const float4*)s_tl;
        float4 tr = *(const float4*)s_tr;
        float4 bl = *(const float4*)s_bl;
        float4 br = *(const float4*)s_br;
        float4 res;
        {
            float top, bot;
            top = tl.x + (tr.x - tl.x) * lx;
            bot = bl.x + (br.x - bl.x) * lx;
            res.x = top + (bot - top) * ly;
            top = tl.y + (tr.y - tl.y) * lx;
            bot = bl.y + (br.y - bl.y) * lx;
            res.y = top + (bot - top) * ly;
            top = tl.z + (tr.z - tl.z) * lx;
            bot = bl.z + (br.z - bl.z) * lx;
            res.z = top + (bot - top) * ly;
            top = tl.w + (tr.w - tl.w) * lx;
            bot = bl.w + (br.w - bl.w) * lx;
            res.w = top + (bot - top) * ly;
        }
        stg_wt(ocell, res);
    }
}

extern "C" void kernel_launch(void* const* d_in, const int* in_sizes, int n_in,
                              void* d_out, int out_size)
{
    const float* img  = (const float*)d_in[0];
    const float* rois = (const float*)d_in[1];
    float* out = (float*)d_out;

    cudaFuncSetAttribute(k_process, cudaFuncAttributeMaxDynamicSharedMemorySize,
                         SMEM_BYTES);

    void* cnt_ptr = nullptr;
    cudaGetSymbolAddress(&cnt_ptr, g_cnt);
    cudaMemsetAsync(cnt_ptr, 0, NT * sizeof(int), 0);

    k_bin<<<(N_CELLS + 255) / 256, 256>>>(rois);
    k_process<<<NT * 2, 256, SMEM_BYTES>>>(img, out);
}

// round 10
// speedup vs baseline: 1.4636x; 1.0918x over previous
#include <cuda_runtime.h>

#define IMG_B 8
#define IMG_H 100
#define IMG_W 100
#define IMG_C 256
#define OUT_HW 7
#define CELLS 49
#define N_CELLS (2000 * CELLS)      // 98000

#define TS 8
#define TG 13
#define NT (IMG_B * TG * TG)        // 1352
#define CAP 1024

__device__ int g_cnt[NT];
__device__ int g_list[NT * CAP];

// plain 256-bit image load via read-only (nc) path -> allocates in L1
__device__ __forceinline__ void ldg256(const float* p, float4* d) {
    unsigned r0, r1, r2, r3, r4, r5, r6, r7;
    asm volatile("ld.global.nc.v8.b32 {%0,%1,%2,%3,%4,%5,%6,%7}, [%8];"
                 : "=r"(r0), "=r"(r1), "=r"(r2), "=r"(r3),
                   "=r"(r4), "=r"(r5), "=r"(r6), "=r"(r7) : "l"(p));
    d[0] = make_float4(__uint_as_float(r0), __uint_as_float(r1),
                       __uint_as_float(r2), __uint_as_float(r3));
    d[1] = make_float4(__uint_as_float(r4), __uint_as_float(r5),
                       __uint_as_float(r6), __uint_as_float(r7));
}

// ---- pass 1: bin cell ids by the 8x8 tile containing the clamped TL corner ----
__global__ void k_bin(const float* __restrict__ rois)
{
    int cell = blockIdx.x * blockDim.x + threadIdx.x;
    if (cell >= N_CELLS) return;

    int roi = cell / CELLS;
    int rem = cell - roi * CELLS;
    int oy = rem / OUT_HW;
    int ox = rem - oy * OUT_HW;

    const float* r = rois + roi * 5;
    float rb  = __ldg(r + 0);
    float rx1 = __ldg(r + 1);
    float ry1 = __ldg(r + 2);
    float rx2 = __ldg(r + 3);
    float ry2 = __ldg(r + 4);

    float x1 = rx1 * (1.0f / IMG_W);
    float x2 = rx2 * (1.0f / IMG_W);
    float y1 = ry1 * (1.0f / IMG_H);
    float y2 = ry2 * (1.0f / IMG_H);

    float in_y = y1 * (float)(IMG_H - 1)
               + (float)oy * ((y2 - y1) * (float)(IMG_H - 1) / (float)(OUT_HW - 1));
    float in_x = x1 * (float)(IMG_W - 1)
               + (float)ox * ((x2 - x1) * (float)(IMG_W - 1) / (float)(OUT_HW - 1));

    int ty = min(max((int)floorf(in_y), 0), IMG_H - 1);
    int tx = min(max((int)floorf(in_x), 0), IMG_W - 1);

    int t = ((int)rb * TG + (ty >> 3)) * TG + (tx >> 3);
    int pos = atomicAdd(&g_cnt[t], 1);
    if (pos < CAP) g_list[t * CAP + pos] = cell;
}

// ---- pass 2: flat gather (R4 pipeline), but block = one spatial tile ----
// No smem, no barriers. All corner reads of this block fall in a ~81KB
// neighborhood -> served from L1 after first touch (L1 does the dedup).
__global__ void __launch_bounds__(256, 6)
k_process(const float* __restrict__ img,
          const float* __restrict__ rois,
          float* __restrict__ out)
{
    int t = blockIdx.x;
    int cnt = min(g_cnt[t], CAP);
    if (cnt == 0) return;

    int warp = threadIdx.x >> 5;
    int lane = threadIdx.x & 31;
    int ch   = lane * 8;

    const int* list = g_list + t * CAP;

    for (int i = warp; i < cnt; i += 8) {
        int cell = __ldg(list + i);

        int roi = cell / CELLS;
        int rem = cell - roi * CELLS;
        int oy = rem / OUT_HW;
        int ox = rem - oy * OUT_HW;

        const float* r = rois + roi * 5;
        float rb  = __ldg(r + 0);
        float rx1 = __ldg(r + 1);
        float ry1 = __ldg(r + 2);
        float rx2 = __ldg(r + 3);
        float ry2 = __ldg(r + 4);

        int b = (int)rb;

        float x1 = rx1 * (1.0f / IMG_W);
        float x2 = rx2 * (1.0f / IMG_W);
        float y1 = ry1 * (1.0f / IMG_H);
        float y2 = ry2 * (1.0f / IMG_H);

        float in_y = y1 * (float)(IMG_H - 1)
                   + (float)oy * ((y2 - y1) * (float)(IMG_H - 1) / (float)(OUT_HW - 1));
        float in_x = x1 * (float)(IMG_W - 1)
                   + (float)ox * ((x2 - x1) * (float)(IMG_W - 1) / (float)(OUT_HW - 1));

        float* ocell = out + (size_t)cell * IMG_C + ch;

        bool valid = (in_y >= 0.0f) && (in_y <= (float)(IMG_H - 1)) &&
                     (in_x >= 0.0f) && (in_x <= (float)(IMG_W - 1));
        if (!valid) {
            float4 z = make_float4(0.f, 0.f, 0.f, 0.f);
            __stcs((float4*)ocell, z);
            __stcs((float4*)ocell + 1, z);
            continue;
        }

        float fy = floorf(in_y);
        float fx = floorf(in_x);
        float ly = in_y - fy;
        float lx = in_x - fx;

        int ty = min(max((int)fy, 0), IMG_H - 1);
        int by = min(max((int)ceilf(in_y), 0), IMG_H - 1);
        int tx = min(max((int)fx, 0), IMG_W - 1);
        int bx = min(max((int)ceilf(in_x), 0), IMG_W - 1);

        int row_t = (b * IMG_H + ty) * IMG_W;
        int row_b = (b * IMG_H + by) * IMG_W;

        const float* p_tl = img + (size_t)(row_t + tx) * IMG_C + ch;
        const float* p_tr = img + (size_t)(row_t + bx) * IMG_C + ch;
        const float* p_bl = img + (size_t)(row_b + tx) * IMG_C + ch;
        const float* p_br = img + (size_t)(row_b + bx) * IMG_C + ch;

        float4 tl[2], tr[2], bl[2], br[2];
        ldg256(p_tl, tl);
        ldg256(p_tr, tr);
        ldg256(p_bl, bl);
        ldg256(p_br, br);

        float4 res[2];
        #pragma unroll
        for (int h = 0; h < 2; h++) {
            float top, bot;
            top = tl[h].x + (tr[h].x - tl[h].x) * lx;
            bot = bl[h].x + (br[h].x - bl[h].x) * lx;
            res[h].x = top + (bot - top) * ly;
            top = tl[h].y + (tr[h].y - tl[h].y) * lx;
            bot = bl[h].y + (br[h].y - bl[h].y) * lx;
            res[h].y = top + (bot - top) * ly;
            top = tl[h].z + (tr[h].z - tl[h].z) * lx;
            bot = bl[h].z + (br[h].z - bl[h].z) * lx;
            res[h].z = top + (bot - top) * ly;
            top = tl[h].w + (tr[h].w - tl[h].w) * lx;
            bot = bl[h].w + (br[h].w - bl[h].w) * lx;
            res[h].w = top + (bot - top) * ly;
        }

        __stcs((float4*)ocell, res[0]);
        __stcs((float4*)ocell + 1, res[1]);
    }
}

extern "C" void kernel_launch(void* const* d_in, const int* in_sizes, int n_in,
                              void* d_out, int out_size)
{
    const float* img  = (const float*)d_in[0];
    const float* rois = (const float*)d_in[1];
    float* out = (float*)d_out;

    void* cnt_ptr = nullptr;
    cudaGetSymbolAddress(&cnt_ptr, g_cnt);
    cudaMemsetAsync(cnt_ptr, 0, NT * sizeof(int), 0);

    k_bin<<<(N_CELLS + 255) / 256, 256>>>(rois);
    k_process<<<NT, 256>>>(img, rois, out);
}

// round 11
// speedup vs baseline: 1.5687x; 1.0718x over previous
#include <cuda_runtime.h>

#define IMG_B 8
#define IMG_H 100
#define IMG_W 100
#define IMG_C 256
#define OUT_HW 7
#define CELLS 49
#define N_CELLS (2000 * CELLS)      // 98000

#define TS 8
#define TG 13
#define NT (IMG_B * TG * TG)        // 1352
#define CAP 1024
#define CHUNK 64
#define MAXCHUNK 16                 // CHUNK*MAXCHUNK == CAP

__device__ int  g_cnt[NT];
__device__ int4 g_geo[NT * CAP];    // {cell|valid<<30, packed(ty,by,tx,bx), ly, lx}

// 256-bit image load via read-only (nc) path -> allocates in L1 (dedup engine)
__device__ __forceinline__ void ldg256(const float* p, float4* d) {
    unsigned r0, r1, r2, r3, r4, r5, r6, r7;
    asm volatile("ld.global.nc.v8.b32 {%0,%1,%2,%3,%4,%5,%6,%7}, [%8];"
                 : "=r"(r0), "=r"(r1), "=r"(r2), "=r"(r3),
                   "=r"(r4), "=r"(r5), "=r"(r6), "=r"(r7) : "l"(p));
    d[0] = make_float4(__uint_as_float(r0), __uint_as_float(r1),
                       __uint_as_float(r2), __uint_as_float(r3));
    d[1] = make_float4(__uint_as_float(r4), __uint_as_float(r5),
                       __uint_as_float(r6), __uint_as_float(r7));
}

// ---- pass 1: full geometry once per cell, binned by TL-corner tile ----
__global__ void k_bin(const float* __restrict__ rois)
{
    int cell = blockIdx.x * blockDim.x + threadIdx.x;
    if (cell >= N_CELLS) return;

    int roi = cell / CELLS;
    int rem = cell - roi * CELLS;
    int oy = rem / OUT_HW;
    int ox = rem - oy * OUT_HW;

    const float* r = rois + roi * 5;
    float rb  = __ldg(r + 0);
    float rx1 = __ldg(r + 1);
    float ry1 = __ldg(r + 2);
    float rx2 = __ldg(r + 3);
    float ry2 = __ldg(r + 4);

    float x1 = rx1 * (1.0f / IMG_W);
    float x2 = rx2 * (1.0f / IMG_W);
    float y1 = ry1 * (1.0f / IMG_H);
    float y2 = ry2 * (1.0f / IMG_H);

    float in_y = y1 * (float)(IMG_H - 1)
               + (float)oy * ((y2 - y1) * (float)(IMG_H - 1) / (float)(OUT_HW - 1));
    float in_x = x1 * (float)(IMG_W - 1)
               + (float)ox * ((x2 - x1) * (float)(IMG_W - 1) / (float)(OUT_HW - 1));

    bool valid = (in_y >= 0.0f) && (in_y <= (float)(IMG_H - 1)) &&
                 (in_x >= 0.0f) && (in_x <= (float)(IMG_W - 1));

    float fy = floorf(in_y);
    float fx = floorf(in_x);
    float ly = in_y - fy;
    float lx = in_x - fx;
    int ty = min(max((int)fy, 0), IMG_H - 1);
    int by = min(max((int)ceilf(in_y), 0), IMG_H - 1);
    int tx = min(max((int)fx, 0), IMG_W - 1);
    int bx = min(max((int)ceilf(in_x), 0), IMG_W - 1);

    int t = ((int)rb * TG + (ty >> 3)) * TG + (tx >> 3);

    int4 rec;
    rec.x = cell | (valid ? (1 << 30) : 0) | ((int)rb << 24);
    rec.y = ty | (by << 8) | (tx << 16) | (bx << 24);
    rec.z = __float_as_int(ly);
    rec.w = __float_as_int(lx);

    int pos = atomicAdd(&g_cnt[t], 1);
    if (pos < CAP) g_geo[t * CAP + pos] = rec;
}

// ---- pass 2: block = (tile, chunk of 64 cells). No smem; L1 dedups the
// spatially-clustered corner reads. 8 warps; warp = one cell per iteration,
// max 8 iterations -> no straggler blocks. Next-rec prefetch hides list latency.
__global__ void __launch_bounds__(256, 6)
k_process(const float* __restrict__ img, float* __restrict__ out)
{
    int bid   = blockIdx.x;
    int t     = bid >> 4;
    int chunk = bid & (MAXCHUNK - 1);

    int cnt = min(g_cnt[t], CAP);
    int i_beg = chunk * CHUNK;
    if (i_beg >= cnt) return;
    int i_end = min(cnt, i_beg + CHUNK);

    int warp = threadIdx.x >> 5;
    int lane = threadIdx.x & 31;
    int ch   = lane * 8;

    const int4* list = g_geo + t * CAP;

    int i = i_beg + warp;
    if (i >= i_end) return;

    int4 rec = __ldg(list + i);

    for (; i < i_end; i += 8) {
        int inext = i + 8;
        int4 nrec = (inext < i_end) ? __ldg(list + inext) : rec;

        int  cell  = rec.x & 0x00FFFFFF;
        int  b     = (rec.x >> 24) & 0xF;
        bool valid = (rec.x >> 30) & 1;

        float* ocell = out + (size_t)cell * IMG_C + ch;

        if (valid) {
            int ty = rec.y & 0xFF;
            int by = (rec.y >> 8) & 0xFF;
            int tx = (rec.y >> 16) & 0xFF;
            int bx = (rec.y >> 24) & 0xFF;
            float ly = __int_as_float(rec.z);
            float lx = __int_as_float(rec.w);

            int row_t = (b * IMG_H + ty) * IMG_W;
            int row_b = (b * IMG_H + by) * IMG_W;

            const float* p_tl = img + (size_t)(row_t + tx) * IMG_C + ch;
            const float* p_tr = img + (size_t)(row_t + bx) * IMG_C + ch;
            const float* p_bl = img + (size_t)(row_b + tx) * IMG_C + ch;
            const float* p_br = img + (size_t)(row_b + bx) * IMG_C + ch;

            float4 tl[2], tr[2], bl[2], br[2];
            ldg256(p_tl, tl);
            ldg256(p_tr, tr);
            ldg256(p_bl, bl);
            ldg256(p_br, br);

            float4 res[2];
            #pragma unroll
            for (int h = 0; h < 2; h++) {
                float top, bot;
                top = tl[h].x + (tr[h].x - tl[h].x) * lx;
                bot = bl[h].x + (br[h].x - bl[h].x) * lx;
                res[h].x = top + (bot - top) * ly;
                top = tl[h].y + (tr[h].y - tl[h].y) * lx;
                bot = bl[h].y + (br[h].y - bl[h].y) * lx;
                res[h].y = top + (bot - top) * ly;
                top = tl[h].z + (tr[h].z - tl[h].z) * lx;
                bot = bl[h].z + (br[h].z - bl[h].z) * lx;
                res[h].z = top + (bot - top) * ly;
                top = tl[h].w + (tr[h].w - tl[h].w) * lx;
                bot = bl[h].w + (br[h].w - bl[h].w) * lx;
                res[h].w = top + (bot - top) * ly;
            }
            __stcs((float4*)ocell, res[0]);
            __stcs((float4*)ocell + 1, res[1]);
        } else {
            float4 z = make_float4(0.f, 0.f, 0.f, 0.f);
            __stcs((float4*)ocell, z);
            __stcs((float4*)ocell + 1, z);
        }

        rec = nrec;
    }
}

extern "C" void kernel_launch(void* const* d_in, const int* in_sizes, int n_in,
                              void* d_out, int out_size)
{
    const float* img  = (const float*)d_in[0];
    const float* rois = (const float*)d_in[1];
    float* out = (float*)d_out;

    void* cnt_ptr = nullptr;
    cudaGetSymbolAddress(&cnt_ptr, g_cnt);
    cudaMemsetAsync(cnt_ptr, 0, NT * sizeof(int), 0);

    k_bin<<<(N_CELLS + 255) / 256, 256>>>(rois);
    k_process<<<NT * MAXCHUNK, 256>>>(img, out);
}